// round 4
// baseline (speedup 1.0000x reference)
#include <cuda_runtime.h>
#include <cstdint>

#define NN_D 128
#define NN_BETA 0.001f
#define NN_EPS 1e-12f

#define MAX_N 100000
#define MAX_E 1600000
#define SCAN_BLK 1024

// Scratch (device globals: no runtime allocation allowed).
__device__ float g_support[MAX_N * NN_D];      // 51.2 MB
__device__ int   g_rowptr[MAX_N + 1];
__device__ int   g_cursor[MAX_N];
__device__ int   g_chunksum[128];
__device__ int2  g_ecolval[MAX_E];             // {col, val bits} 12.8 MB

// ---------------------------------------------------------------------------
// Kernel 1: support = input @ weight via tf32 tensor-core mma (3xTF32 split).
// Block: 256 thr / 8 warps. Block tile 128x128, K=128 in one pass.
// Warp tile: 32 rows x 64 cols (2 m-subtiles x 8 n-tiles of m16n8k8).
// Smem rows padded to 132 floats -> conflict-free fragment LDS.
// ---------------------------------------------------------------------------
#define GPAD 132
#define GEMM_BM 128

__device__ __forceinline__ uint32_t f2tf32(float x) {
    uint32_t y;
    asm("cvt.rna.tf32.f32 %0, %1;" : "=r"(y) : "f"(x));
    return y;
}

__device__ __forceinline__ void mma_tf32(
    float4& d,
    uint32_t a0, uint32_t a1, uint32_t a2, uint32_t a3,
    uint32_t b0, uint32_t b1)
{
    asm volatile(
        "mma.sync.aligned.m16n8k8.row.col.f32.tf32.tf32.f32 "
        "{%0,%1,%2,%3}, {%4,%5,%6,%7}, {%8,%9}, {%0,%1,%2,%3};"
        : "+f"(d.x), "+f"(d.y), "+f"(d.z), "+f"(d.w)
        : "r"(a0), "r"(a1), "r"(a2), "r"(a3), "r"(b0), "r"(b1));
}

__global__ __launch_bounds__(256, 1) void nngc_gemm_tf32_kernel(
    const float* __restrict__ input,
    const float* __restrict__ weight,
    int n)
{
    extern __shared__ float sm[];
    float* a_s  = sm;                     // [128][GPAD]
    float* wt_s = sm + GEMM_BM * GPAD;    // [128 n][GPAD k] (weight transposed)

    const int tid  = threadIdx.x;
    const int w    = tid >> 5;
    const int lane = tid & 31;
    const int gid  = lane >> 2;   // group id 0..7
    const int tig  = lane & 3;    // thread in group 0..3

    const int row0 = blockIdx.x * GEMM_BM;

    // --- Load A tile [128 x 128] coalesced, rows >= n zero-filled ---
    {
        const float4 z = make_float4(0.f, 0.f, 0.f, 0.f);
#pragma unroll
        for (int i = 0; i < 16; i++) {
            int idx = tid + i * 256;          // over 128*32 float4 slots
            int r  = idx >> 5;
            int k4 = idx & 31;
            float4 v = z;
            if (row0 + r < n)
                v = *(const float4*)(input + (size_t)(row0 + r) * NN_D + 4 * k4);
            *(float4*)(a_s + r * GPAD + 4 * k4) = v;
        }
    }
    // --- Load weight [K x N] and transpose into wt_s[n][k] ---
    {
#pragma unroll
        for (int i = 0; i < 16; i++) {
            int idx = tid + i * 256;          // over 128*32 float4 slots
            int kr = idx >> 5;
            int n4 = idx & 31;
            float4 v = *(const float4*)(weight + (size_t)kr * NN_D + 4 * n4);
            wt_s[(4 * n4 + 0) * GPAD + kr] = v.x;
            wt_s[(4 * n4 + 1) * GPAD + kr] = v.y;
            wt_s[(4 * n4 + 2) * GPAD + kr] = v.z;
            wt_s[(4 * n4 + 3) * GPAD + kr] = v.w;
        }
    }
    __syncthreads();

    const int mrow = (w & 3) * 32;   // warp row base within tile
    const int ncol = (w >> 2) * 64;  // warp col base within tile

    float4 acc[2][8];
#pragma unroll
    for (int t = 0; t < 2; t++)
#pragma unroll
        for (int j = 0; j < 8; j++)
            acc[t][j] = make_float4(0.f, 0.f, 0.f, 0.f);

#pragma unroll 4
    for (int c = 0; c < 16; c++) {
        const int kc = c * 8 + tig;
        uint32_t ah[2][4], al[2][4];
#pragma unroll
        for (int t = 0; t < 2; t++) {
            const int lr0 = mrow + t * 16 + gid;
            const int lr1 = lr0 + 8;
            float a0 = a_s[lr0 * GPAD + kc];
            float a1 = a_s[lr1 * GPAD + kc];
            float a2 = a_s[lr0 * GPAD + kc + 4];
            float a3 = a_s[lr1 * GPAD + kc + 4];
            ah[t][0] = f2tf32(a0); al[t][0] = f2tf32(a0 - __uint_as_float(ah[t][0]));
            ah[t][1] = f2tf32(a1); al[t][1] = f2tf32(a1 - __uint_as_float(ah[t][1]));
            ah[t][2] = f2tf32(a2); al[t][2] = f2tf32(a2 - __uint_as_float(ah[t][2]));
            ah[t][3] = f2tf32(a3); al[t][3] = f2tf32(a3 - __uint_as_float(ah[t][3]));
        }
#pragma unroll
        for (int j = 0; j < 8; j++) {
            const int nc = ncol + j * 8 + gid;
            float b0f = wt_s[nc * GPAD + kc];
            float b1f = wt_s[nc * GPAD + kc + 4];
            uint32_t bh0 = f2tf32(b0f);
            uint32_t bh1 = f2tf32(b1f);
            uint32_t bl0 = f2tf32(b0f - __uint_as_float(bh0));
            uint32_t bl1 = f2tf32(b1f - __uint_as_float(bh1));
#pragma unroll
            for (int t = 0; t < 2; t++) {
                mma_tf32(acc[t][j], ah[t][0], ah[t][1], ah[t][2], ah[t][3], bl0, bl1);
                mma_tf32(acc[t][j], al[t][0], al[t][1], al[t][2], al[t][3], bh0, bh1);
                mma_tf32(acc[t][j], ah[t][0], ah[t][1], ah[t][2], ah[t][3], bh0, bh1);
            }
        }
    }

    // --- Epilogue: store accumulators ---
#pragma unroll
    for (int t = 0; t < 2; t++) {
#pragma unroll
        for (int j = 0; j < 8; j++) {
            const int col = ncol + j * 8 + 2 * tig;
            const int r01 = row0 + mrow + t * 16 + gid;
            const int r23 = r01 + 8;
            if (r01 < n)
                *(float2*)(g_support + (size_t)r01 * NN_D + col) =
                    make_float2(acc[t][j].x, acc[t][j].y);
            if (r23 < n)
                *(float2*)(g_support + (size_t)r23 * NN_D + col) =
                    make_float2(acc[t][j].z, acc[t][j].w);
        }
    }
}

// ---------------------------------------------------------------------------
// CSR build: zero -> hist -> scan(3 kernels) -> scatter
// ---------------------------------------------------------------------------
__global__ void nngc_zero_kernel(int n)
{
    int i = blockIdx.x * 256 + threadIdx.x;
    if (i < n) g_cursor[i] = 0;
}

__global__ void nngc_hist_kernel(const int* __restrict__ erows, int E)
{
    int i = blockIdx.x * 256 + threadIdx.x;
    if (i < E) atomicAdd(&g_cursor[erows[i]], 1);
}

__global__ __launch_bounds__(SCAN_BLK) void nngc_scan1_kernel(int n)
{
    __shared__ int warpsums[32];
    const int i = blockIdx.x * SCAN_BLK + threadIdx.x;
    const int lane = threadIdx.x & 31;
    const int wid = threadIdx.x >> 5;

    int v = (i < n) ? g_cursor[i] : 0;
    int x = v;
#pragma unroll
    for (int o = 1; o < 32; o <<= 1) {
        int t = __shfl_up_sync(0xFFFFFFFFu, x, o);
        if (lane >= o) x += t;
    }
    if (lane == 31) warpsums[wid] = x;
    __syncthreads();
    if (wid == 0) {
        int s = warpsums[lane];
#pragma unroll
        for (int o = 1; o < 32; o <<= 1) {
            int t = __shfl_up_sync(0xFFFFFFFFu, s, o);
            if (lane >= o) s += t;
        }
        warpsums[lane] = s;
    }
    __syncthreads();
    const int wofs = (wid > 0) ? warpsums[wid - 1] : 0;
    if (i < n) g_rowptr[i] = wofs + x - v;  // exclusive
    if (threadIdx.x == SCAN_BLK - 1) g_chunksum[blockIdx.x] = wofs + x;
}

__global__ __launch_bounds__(128) void nngc_scan2_kernel(int nchunks, int n, int E)
{
    __shared__ int s[128];
    const int t = threadIdx.x;
    s[t] = (t < nchunks) ? g_chunksum[t] : 0;
    __syncthreads();
#pragma unroll
    for (int o = 1; o < 128; o <<= 1) {
        int v = (t >= o) ? s[t - o] : 0;
        __syncthreads();
        s[t] += v;
        __syncthreads();
    }
    if (t < nchunks) g_chunksum[t] = (t > 0) ? s[t - 1] : 0;  // exclusive
    if (t == 0) g_rowptr[n] = E;
}

__global__ __launch_bounds__(SCAN_BLK) void nngc_scan3_kernel(int n)
{
    const int i = blockIdx.x * SCAN_BLK + threadIdx.x;
    if (i < n) {
        int v = g_rowptr[i] + g_chunksum[blockIdx.x];
        g_rowptr[i] = v;
        g_cursor[i] = v;
    }
}

__global__ void nngc_scatter_kernel(
    const int* __restrict__ erows,
    const int* __restrict__ ecols,
    const float* __restrict__ evals,
    int E)
{
    int i = blockIdx.x * 256 + threadIdx.x;
    if (i < E) {
        int r = erows[i];
        int pos = atomicAdd(&g_cursor[r], 1);
        g_ecolval[pos] = make_int2(ecols[i], __float_as_int(evals[i]));
    }
}

// ---------------------------------------------------------------------------
// Fused aggregate + blend + normalize + bias. One warp per node.
// ---------------------------------------------------------------------------
__global__ __launch_bounds__(256) void nngc_agg_kernel(
    const float* __restrict__ input,
    const float* __restrict__ bias,
    float* __restrict__ out,
    int n)
{
    const int node = (blockIdx.x * 256 + threadIdx.x) >> 5;
    const int lane = threadIdx.x & 31;
    if (node >= n) return;

    const int start = __ldg(&g_rowptr[node]);
    const int end   = __ldg(&g_rowptr[node + 1]);

    const float4* sup = (const float4*)g_support;
    float4 acc = make_float4(0.f, 0.f, 0.f, 0.f);

    int e = start;
    for (; e + 1 < end; e += 2) {
        const int2 cv0 = __ldg(&g_ecolval[e]);
        const int2 cv1 = __ldg(&g_ecolval[e + 1]);
        const float v0 = __int_as_float(cv0.y);
        const float v1 = __int_as_float(cv1.y);
        const float4 s0 = sup[(size_t)cv0.x * 32 + lane];
        const float4 s1 = sup[(size_t)cv1.x * 32 + lane];
        acc.x += v0 * s0.x + v1 * s1.x;
        acc.y += v0 * s0.y + v1 * s1.y;
        acc.z += v0 * s0.z + v1 * s1.z;
        acc.w += v0 * s0.w + v1 * s1.w;
    }
    if (e < end) {
        const int2 cv = __ldg(&g_ecolval[e]);
        const float v = __int_as_float(cv.y);
        const float4 s = sup[(size_t)cv.x * 32 + lane];
        acc.x += v * s.x; acc.y += v * s.y;
        acc.z += v * s.z; acc.w += v * s.w;
    }

    const float4 x = ((const float4*)(input + (size_t)node * NN_D))[lane];
    const float omb = 1.f - NN_BETA;
    float4 o;
    o.x = NN_BETA * x.x + omb * acc.x;
    o.y = NN_BETA * x.y + omb * acc.y;
    o.z = NN_BETA * x.z + omb * acc.z;
    o.w = NN_BETA * x.w + omb * acc.w;

    float ss = o.x * o.x + o.y * o.y + o.z * o.z + o.w * o.w;
#pragma unroll
    for (int m = 16; m > 0; m >>= 1)
        ss += __shfl_xor_sync(0xFFFFFFFFu, ss, m);

    const float rn = 1.f / fmaxf(sqrtf(ss), NN_EPS);
    const float4 b = ((const float4*)bias)[lane];

    o.x = o.x * rn + b.x;
    o.y = o.y * rn + b.y;
    o.z = o.z * rn + b.z;
    o.w = o.w * rn + b.w;

    ((float4*)(out + (size_t)node * NN_D))[lane] = o;
}

// ---------------------------------------------------------------------------
// Launch
// ---------------------------------------------------------------------------
extern "C" void kernel_launch(void* const* d_in, const int* in_sizes, int n_in,
                              void* d_out, int out_size)
{
    const float* input  = (const float*)d_in[0];
    const int*   erows  = (const int*)d_in[1];
    const int*   ecols  = (const int*)d_in[2];
    const float* evals  = (const float*)d_in[3];
    const float* weight = (const float*)d_in[4];
    const float* bias   = (const float*)d_in[5];
    float* out = (float*)d_out;

    const int n = in_sizes[0] / NN_D;   // 100000
    const int E = in_sizes[1];          // 1600000

    const int gemm_smem = 2 * GEMM_BM * GPAD * (int)sizeof(float);  // 135168
    cudaFuncSetAttribute(nngc_gemm_tf32_kernel,
                         cudaFuncAttributeMaxDynamicSharedMemorySize,
                         gemm_smem);

    // GEMM (tf32 tensor cores, 3xTF32 split)
    const int gemm_blocks = (n + GEMM_BM - 1) / GEMM_BM;
    nngc_gemm_tf32_kernel<<<gemm_blocks, 256, gemm_smem>>>(input, weight, n);

    // CSR build
    const int nchunks = (n + SCAN_BLK - 1) / SCAN_BLK;
    nngc_zero_kernel<<<(n + 255) / 256, 256>>>(n);
    nngc_hist_kernel<<<(E + 255) / 256, 256>>>(erows, E);
    nngc_scan1_kernel<<<nchunks, SCAN_BLK>>>(n);
    nngc_scan2_kernel<<<1, 128>>>(nchunks, n, E);
    nngc_scan3_kernel<<<nchunks, SCAN_BLK>>>(n);
    nngc_scatter_kernel<<<(E + 255) / 256, 256>>>(erows, ecols, evals, E);

    // Fused aggregate + finalize
    nngc_agg_kernel<<<(n + 7) / 8, 256>>>(input, bias, out, n);
}

// round 6
// speedup vs baseline: 1.2346x; 1.2346x over previous
#include <cuda_runtime.h>
#include <cstdint>

#define NN_D 128
#define NN_BETA 0.001f
#define NN_EPS 1e-12f

#define MAX_N 100000
#define MAX_E 1600000
#define SCAN_BLK 1024

// Scratch (device globals: no runtime allocation allowed).
__device__ float g_support[MAX_N * NN_D];      // 51.2 MB
__device__ int   g_rowptr[MAX_N + 1];
__device__ int   g_cursor[MAX_N];
__device__ int   g_chunksum[128];
__device__ int2  g_ecolval[MAX_E];             // {col, val bits} 12.8 MB

// ---------------------------------------------------------------------------
// Packed fp32 helpers (FFMA2 via PTX fma.rn.f32x2 — Blackwell packed math)
// ---------------------------------------------------------------------------
__device__ __forceinline__ unsigned long long pack2(float lo, float hi) {
    unsigned long long r;
    asm("mov.b64 %0, {%1, %2};" : "=l"(r) : "f"(lo), "f"(hi));
    return r;
}
__device__ __forceinline__ void unpack2(unsigned long long v, float& lo, float& hi) {
    asm("mov.b64 {%0, %1}, %2;" : "=f"(lo), "=f"(hi) : "l"(v));
}
__device__ __forceinline__ void ffma2(unsigned long long& d,
                                      unsigned long long a,
                                      unsigned long long b) {
    asm("fma.rn.f32x2 %0, %1, %2, %0;" : "+l"(d) : "l"(a), "l"(b));
}

// ---------------------------------------------------------------------------
// Kernel 1: support = input @ weight, fp32 via packed FFMA2.
// Block: 256 thr, tile 64 rows x 128 cols, K=128 in one pass.
// Thread tile: 4 rows x 8 cols (= 4 f32x2 column pairs).
// Smem: A [64][132] (pad 4 -> conflict-free fills, 16B-aligned rows)
//       W [128][128] row-major (natural f32x2 pairs along n).
// ---------------------------------------------------------------------------
#define GM 64
#define APAD 132

__global__ __launch_bounds__(256, 2) void nngc_gemm_f32x2_kernel(
    const float* __restrict__ input,
    const float* __restrict__ weight,
    int n)
{
    extern __shared__ float sm[];
    float* a_s = sm;                 // [64][APAD]
    float* w_s = sm + GM * APAD;     // [128][128]

    const int tid = threadIdx.x;
    const int row0 = blockIdx.x * GM;

    // --- Fill A tile (coalesced float4 along k; rows >= n zero) ---
    {
        const float4 z = make_float4(0.f, 0.f, 0.f, 0.f);
#pragma unroll
        for (int i = 0; i < 8; i++) {            // 2048 float4 slots
            int idx = tid + i * 256;
            int r  = idx >> 5;                   // 32 float4 per row
            int k4 = (idx & 31) * 4;
            float4 v = z;
            if (row0 + r < n)
                v = *(const float4*)(input + (size_t)(row0 + r) * NN_D + k4);
            *(float4*)(a_s + r * APAD + k4) = v;
        }
    }
    // --- Fill W tile (straight coalesced copy) ---
    {
        const float4* wg = (const float4*)weight;
        float4* ws = (float4*)w_s;
#pragma unroll
        for (int i = 0; i < 16; i++)             // 4096 float4 slots
            ws[tid + i * 256] = wg[tid + i * 256];
    }
    __syncthreads();

    const int tx = tid & 15;        // col group: cols [tx*8, tx*8+8)
    const int ty = tid >> 4;        // row group: rows [ty*4, ty*4+4)
    const float* arow = a_s + ty * 4 * APAD;
    const float* wcol = w_s + tx * 8;

    unsigned long long acc[4][4];
#pragma unroll
    for (int i = 0; i < 4; i++)
#pragma unroll
        for (int j = 0; j < 4; j++) acc[i][j] = 0ull;

#pragma unroll 4
    for (int k = 0; k < NN_D; k++) {
        const float a0 = arow[0 * APAD + k];
        const float a1 = arow[1 * APAD + k];
        const float a2 = arow[2 * APAD + k];
        const float a3 = arow[3 * APAD + k];
        const unsigned long long pa0 = pack2(a0, a0);
        const unsigned long long pa1 = pack2(a1, a1);
        const unsigned long long pa2 = pack2(a2, a2);
        const unsigned long long pa3 = pack2(a3, a3);

        const ulonglong2 b01 = *(const ulonglong2*)(wcol + (size_t)k * NN_D);
        const ulonglong2 b23 = *(const ulonglong2*)(wcol + (size_t)k * NN_D + 4);

        ffma2(acc[0][0], pa0, b01.x); ffma2(acc[0][1], pa0, b01.y);
        ffma2(acc[0][2], pa0, b23.x); ffma2(acc[0][3], pa0, b23.y);
        ffma2(acc[1][0], pa1, b01.x); ffma2(acc[1][1], pa1, b01.y);
        ffma2(acc[1][2], pa1, b23.x); ffma2(acc[1][3], pa1, b23.y);
        ffma2(acc[2][0], pa2, b01.x); ffma2(acc[2][1], pa2, b01.y);
        ffma2(acc[2][2], pa2, b23.x); ffma2(acc[2][3], pa2, b23.y);
        ffma2(acc[3][0], pa3, b01.x); ffma2(acc[3][1], pa3, b01.y);
        ffma2(acc[3][2], pa3, b23.x); ffma2(acc[3][3], pa3, b23.y);
    }

    // --- Epilogue ---
#pragma unroll
    for (int i = 0; i < 4; i++) {
        const int row = row0 + ty * 4 + i;
        if (row < n) {
            float o[8];
            unpack2(acc[i][0], o[0], o[1]);
            unpack2(acc[i][1], o[2], o[3]);
            unpack2(acc[i][2], o[4], o[5]);
            unpack2(acc[i][3], o[6], o[7]);
            float* dst = g_support + (size_t)row * NN_D + tx * 8;
            *(float4*)(dst)     = make_float4(o[0], o[1], o[2], o[3]);
            *(float4*)(dst + 4) = make_float4(o[4], o[5], o[6], o[7]);
        }
    }
}

// ---------------------------------------------------------------------------
// CSR build: zero -> hist -> scan(3 kernels) -> scatter
// ---------------------------------------------------------------------------
__global__ void nngc_zero_kernel(int n)
{
    int i = blockIdx.x * 256 + threadIdx.x;
    if (i < n) g_cursor[i] = 0;
}

__global__ void nngc_hist_kernel(const int* __restrict__ erows, int E)
{
    int i = blockIdx.x * 256 + threadIdx.x;
    if (i < E) atomicAdd(&g_cursor[erows[i]], 1);
}

__global__ __launch_bounds__(SCAN_BLK) void nngc_scan1_kernel(int n)
{
    __shared__ int warpsums[32];
    const int i = blockIdx.x * SCAN_BLK + threadIdx.x;
    const int lane = threadIdx.x & 31;
    const int wid = threadIdx.x >> 5;

    int v = (i < n) ? g_cursor[i] : 0;
    int x = v;
#pragma unroll
    for (int o = 1; o < 32; o <<= 1) {
        int t = __shfl_up_sync(0xFFFFFFFFu, x, o);
        if (lane >= o) x += t;
    }
    if (lane == 31) warpsums[wid] = x;
    __syncthreads();
    if (wid == 0) {
        int s = warpsums[lane];
#pragma unroll
        for (int o = 1; o < 32; o <<= 1) {
            int t = __shfl_up_sync(0xFFFFFFFFu, s, o);
            if (lane >= o) s += t;
        }
        warpsums[lane] = s;
    }
    __syncthreads();
    const int wofs = (wid > 0) ? warpsums[wid - 1] : 0;
    if (i < n) g_rowptr[i] = wofs + x - v;  // exclusive
    if (threadIdx.x == SCAN_BLK - 1) g_chunksum[blockIdx.x] = wofs + x;
}

__global__ __launch_bounds__(128) void nngc_scan2_kernel(int nchunks, int n, int E)
{
    __shared__ int s[128];
    const int t = threadIdx.x;
    s[t] = (t < nchunks) ? g_chunksum[t] : 0;
    __syncthreads();
#pragma unroll
    for (int o = 1; o < 128; o <<= 1) {
        int v = (t >= o) ? s[t - o] : 0;
        __syncthreads();
        s[t] += v;
        __syncthreads();
    }
    if (t < nchunks) g_chunksum[t] = (t > 0) ? s[t - 1] : 0;  // exclusive
    if (t == 0) g_rowptr[n] = E;
}

__global__ __launch_bounds__(SCAN_BLK) void nngc_scan3_kernel(int n)
{
    const int i = blockIdx.x * SCAN_BLK + threadIdx.x;
    if (i < n) {
        int v = g_rowptr[i] + g_chunksum[blockIdx.x];
        g_rowptr[i] = v;
        g_cursor[i] = v;
    }
}

__global__ void nngc_scatter_kernel(
    const int* __restrict__ erows,
    const int* __restrict__ ecols,
    const float* __restrict__ evals,
    int E)
{
    int i = blockIdx.x * 256 + threadIdx.x;
    if (i < E) {
        int r = erows[i];
        int pos = atomicAdd(&g_cursor[r], 1);
        g_ecolval[pos] = make_int2(ecols[i], __float_as_int(evals[i]));
    }
}

// ---------------------------------------------------------------------------
// Fused aggregate + blend + normalize + bias. One warp per node.
// ---------------------------------------------------------------------------
__global__ __launch_bounds__(256) void nngc_agg_kernel(
    const float* __restrict__ input,
    const float* __restrict__ bias,
    float* __restrict__ out,
    int n)
{
    const int node = (blockIdx.x * 256 + threadIdx.x) >> 5;
    const int lane = threadIdx.x & 31;
    if (node >= n) return;

    const int start = __ldg(&g_rowptr[node]);
    const int end   = __ldg(&g_rowptr[node + 1]);

    const float4* sup = (const float4*)g_support;
    float4 acc = make_float4(0.f, 0.f, 0.f, 0.f);

    int e = start;
    for (; e + 1 < end; e += 2) {
        const int2 cv0 = __ldg(&g_ecolval[e]);
        const int2 cv1 = __ldg(&g_ecolval[e + 1]);
        const float v0 = __int_as_float(cv0.y);
        const float v1 = __int_as_float(cv1.y);
        const float4 s0 = sup[(size_t)cv0.x * 32 + lane];
        const float4 s1 = sup[(size_t)cv1.x * 32 + lane];
        acc.x += v0 * s0.x + v1 * s1.x;
        acc.y += v0 * s0.y + v1 * s1.y;
        acc.z += v0 * s0.z + v1 * s1.z;
        acc.w += v0 * s0.w + v1 * s1.w;
    }
    if (e < end) {
        const int2 cv = __ldg(&g_ecolval[e]);
        const float v = __int_as_float(cv.y);
        const float4 s = sup[(size_t)cv.x * 32 + lane];
        acc.x += v * s.x; acc.y += v * s.y;
        acc.z += v * s.z; acc.w += v * s.w;
    }

    const float4 x = ((const float4*)(input + (size_t)node * NN_D))[lane];
    const float omb = 1.f - NN_BETA;
    float4 o;
    o.x = NN_BETA * x.x + omb * acc.x;
    o.y = NN_BETA * x.y + omb * acc.y;
    o.z = NN_BETA * x.z + omb * acc.z;
    o.w = NN_BETA * x.w + omb * acc.w;

    float ss = o.x * o.x + o.y * o.y + o.z * o.z + o.w * o.w;
#pragma unroll
    for (int m = 16; m > 0; m >>= 1)
        ss += __shfl_xor_sync(0xFFFFFFFFu, ss, m);

    const float rn = 1.f / fmaxf(sqrtf(ss), NN_EPS);
    const float4 b = ((const float4*)bias)[lane];

    o.x = o.x * rn + b.x;
    o.y = o.y * rn + b.y;
    o.z = o.z * rn + b.z;
    o.w = o.w * rn + b.w;

    ((float4*)(out + (size_t)node * NN_D))[lane] = o;
}

// ---------------------------------------------------------------------------
// Launch
// ---------------------------------------------------------------------------
extern "C" void kernel_launch(void* const* d_in, const int* in_sizes, int n_in,
                              void* d_out, int out_size)
{
    const float* input  = (const float*)d_in[0];
    const int*   erows  = (const int*)d_in[1];
    const int*   ecols  = (const int*)d_in[2];
    const float* evals  = (const float*)d_in[3];
    const float* weight = (const float*)d_in[4];
    const float* bias   = (const float*)d_in[5];
    float* out = (float*)d_out;

    const int n = in_sizes[0] / NN_D;   // 100000
    const int E = in_sizes[1];          // 1600000

    const int gemm_smem = (GM * APAD + NN_D * NN_D) * (int)sizeof(float);
    cudaFuncSetAttribute(nngc_gemm_f32x2_kernel,
                         cudaFuncAttributeMaxDynamicSharedMemorySize,
                         gemm_smem);

    // GEMM (packed fp32 FFMA2)
    const int gemm_blocks = (n + GM - 1) / GM;
    nngc_gemm_f32x2_kernel<<<gemm_blocks, 256, gemm_smem>>>(input, weight, n);

    // CSR build
    const int nchunks = (n + SCAN_BLK - 1) / SCAN_BLK;
    nngc_zero_kernel<<<(n + 255) / 256, 256>>>(n);
    nngc_hist_kernel<<<(E + 255) / 256, 256>>>(erows, E);
    nngc_scan1_kernel<<<nchunks, SCAN_BLK>>>(n);
    nngc_scan2_kernel<<<1, 128>>>(nchunks, n, E);
    nngc_scan3_kernel<<<nchunks, SCAN_BLK>>>(n);
    nngc_scatter_kernel<<<(E + 255) / 256, 256>>>(erows, ecols, evals, E);

    // Fused aggregate + finalize
    nngc_agg_kernel<<<(n + 7) / 8, 256>>>(input, bias, out, n);
}